// round 5
// baseline (speedup 1.0000x reference)
#include <cuda_runtime.h>
#include <cuda_bf16.h>
#include <cstdint>

#define BATCH  64
#define NANCH  8400
#define MAXOUT 100
#define TPB    512
#define KPT    17            // 512*17 = 8704 >= 8400
#define DT     512           // decode threads per CTA
#define DAANCH 128           // anchors per decode CTA (4 threads/anchor)
#define NW     4             // speculative winners per NMS round

typedef unsigned long long ull;

// ---------------------------------------------------------------------------
// Scratch
// ---------------------------------------------------------------------------
__device__ float4   g_boxes[BATCH * NANCH];
__device__ unsigned g_keys [BATCH * NANCH];   // monotonic score keys (0 = invalid)
__device__ int      g_labels[BATCH * NANCH];

// ---------------------------------------------------------------------------
// Kernel 1: decode. 512 threads stage 128 anchors (coalesced); 4 threads per
// anchor: lane h computes DFL side h and classes [20h, 20h+20); 2-hop shuffle
// merge (exact first-max / lowest-index tie semantics).
// ---------------------------------------------------------------------------
__global__ void __launch_bounds__(DT) decode_kernel(const float* __restrict__ preds,
                                                    const float* __restrict__ anchors)
{
    extern __shared__ float4 sbuf[];          // 128 * 37 float4 = 75776 B
    const int t   = threadIdx.x;
    const int cta = blockIdx.x;

    const float4* __restrict__ base =
        reinterpret_cast<const float4*>(preds) + (size_t)cta * DAANCH * 36;

    // ---- coalesced stage: 4608 float4, incremental div/mod by 36 ----
    {
        int a = t / 36;
        int j = t - a * 36;
#pragma unroll
        for (int u = 0; u < 9; ++u) {
            sbuf[a * 37 + j] = base[t + u * DT];
            a += 14; j += 8;                   // += 512 = 14*36 + 8
            if (j >= 36) { j -= 36; ++a; }
        }
    }
    __syncthreads();

    const int an = t >> 2;                     // anchor within CTA
    const int h  = t & 3;                      // quarter 0..3
    const float4* mine = sbuf + an * 37;

    // ---- DFL: side h (16 bins) ----
    float d;
    {
        float v[16];
#pragma unroll
        for (int q = 0; q < 4; ++q) {
            float4 f = mine[h * 4 + q];
            v[q * 4 + 0] = f.x; v[q * 4 + 1] = f.y;
            v[q * 4 + 2] = f.z; v[q * 4 + 3] = f.w;
        }
        float m = v[0];
#pragma unroll
        for (int i = 1; i < 16; ++i) m = fmaxf(m, v[i]);
        float se = 0.f, ws = 0.f;
#pragma unroll
        for (int i = 0; i < 16; ++i) {
            float e = __expf(v[i] - m);
            se += e;
            ws = fmaf(e, (float)i, ws);
        }
        d = ws / se;
    }
    // partner side (h0<->h2, h1<->h3): for h<2, d = tl side, dpart = br side
    float dpart = __shfl_xor_sync(0xffffffffu, d, 2);

    // ---- classes: block [20h, 20h+20), sequential first-max ----
    float best = -3.402823466e38f;
    int lab = 0;
#pragma unroll
    for (int i = 0; i < 5; ++i) {
        float4 f = mine[16 + h * 5 + i];
        int c = h * 20 + 4 * i;
        if (f.x > best) { best = f.x; lab = c + 0; }
        if (f.y > best) { best = f.y; lab = c + 1; }
        if (f.z > best) { best = f.z; lab = c + 2; }
        if (f.w > best) { best = f.w; lab = c + 3; }
    }

    // ---- per-dimension box coords (valid for h<2) ----
    const int gid = cta * DAANCH + an;
    const int nn  = gid % NANCH;
    float4 av = reinterpret_cast<const float4*>(anchors)[nn];
    float aa = (h & 1) ? av.y : av.x;
    float ab = (h & 1) ? av.w : av.z;
    float hw = ab - aa;
    float c0 = (aa + ab) * 0.5f;
    float bc = (dpart - d) * 0.5f * hw + c0;
    float bh = (dpart + d) * hw;
    float lo = bc - bh * 0.5f;
    float hi = bc + bh * 0.5f;

    float olo = __shfl_xor_sync(0xffffffffu, lo, 1);
    float ohi = __shfl_xor_sync(0xffffffffu, hi, 1);

    // ---- class merge across quad (lowest class index wins ties) ----
    {
        float ob = __shfl_xor_sync(0xffffffffu, best, 1);
        int   ol = __shfl_xor_sync(0xffffffffu, lab, 1);
        if (ob > best || (ob == best && ol < lab)) { best = ob; lab = ol; }
        ob = __shfl_xor_sync(0xffffffffu, best, 2);
        ol = __shfl_xor_sync(0xffffffffu, lab, 2);
        if (ob > best || (ob == best && ol < lab)) { best = ob; lab = ol; }
    }

    if (h == 0) {
        float4 box; box.x = lo; box.y = olo; box.z = hi; box.w = ohi;
        g_boxes[gid] = box;
    } else if (h == 1) {
        g_keys[gid] = (best > 0.3f) ? (__float_as_uint(best) + 0x80000000u) : 0u;
    } else if (h == 2) {
        g_labels[gid] = lab;
    }
}

// ---------------------------------------------------------------------------
// Kernel 2: greedy NMS, one CTA per image, NW speculative winners per round.
// Boxes register-resident; full table smem-resident for winner fetch.
// Exact greedy semantics. Gather fused.
// ---------------------------------------------------------------------------
__global__ void __launch_bounds__(TPB, 1) nms_kernel(float* __restrict__ out)
{
    extern __shared__ float4 s_allbox[];      // 8400 float4 = 134400 B
    __shared__ ull      s_arr[2][16];
    __shared__ int      s_selj[MAXOUT];
    __shared__ unsigned s_selk[MAXOUT];

    const int b    = blockIdx.x;
    const int t    = threadIdx.x;
    const int warp = t >> 5;
    const int lane = t & 31;

    const float4*   __restrict__ gb = g_boxes + (size_t)b * NANCH;
    const unsigned* __restrict__ gk = g_keys  + (size_t)b * NANCH;

    for (int i = t; i < NANCH; i += TPB) s_allbox[i] = gb[i];
    if (t < MAXOUT) { s_selj[t] = 0; s_selk[t] = 0u; }

    float4   bx[KPT];
    unsigned ky[KPT];
    unsigned lk = 0u;
    int      li = 0;

#pragma unroll
    for (int k = 0; k < KPT; ++k) {
        int idx = t + k * TPB;
        float4 v = make_float4(0.f, 0.f, 0.f, 0.f);
        unsigned kk = 0u;
        if (idx < NANCH) { v = gb[idx]; kk = gk[idx]; }
        bx[k] = v;
        ky[k] = kk;
        if (kk > lk) { lk = kk; li = idx; }      // ascending k -> lowest idx tie
    }
    __syncthreads();

    unsigned alive = 0x1ffffu;                   // per-warp k-chunk liveness
    int emitted = 0;
    int pc = 0;
    bool exhausted = false;
    int guard = 0;

    while (emitted < MAXOUT && !exhausted && guard++ < MAXOUT) {
        int      jw[NW];
        unsigned kw[NW];

        // ---- NW sequential block argmaxes (cheap picks) ----
#pragma unroll
        for (int w = 0; w < NW; ++w) {
            unsigned wm   = __reduce_max_sync(0xffffffffu, lk);
            unsigned cand = (lk == wm) ? (unsigned)li : 0xffffffffu;
            unsigned lim  = __reduce_min_sync(0xffffffffu, cand);
            const int p = pc & 1;
            if (lane == 0)
                s_arr[p][warp] = ((ull)wm << 32) | (unsigned)(65535u - lim);
            __syncthreads();

            ull bestp = s_arr[p][0];
#pragma unroll
            for (int q = 1; q < 16; ++q) {
                ull e = s_arr[p][q];
                if (e > bestp) bestp = e;
            }
            kw[w] = (unsigned)(bestp >> 32);
            jw[w] = 65535 - (int)(bestp & 0xffffffffu);

            // owner retires its winner and refreshes its local max
            if (kw[w] != 0u && t == (jw[w] & (TPB - 1))) {
                int k0 = jw[w] >> 9;             // log2(TPB)
                ky[k0] = 0u;
                if (w < NW - 1) {
                    lk = 0u; li = 0;
#pragma unroll
                    for (int k = 0; k < KPT; ++k)
                        if (ky[k] > lk) { lk = ky[k]; li = t + k * TPB; }
                }
            }
            ++pc;
        }

        // ---- exact greedy simulation among the NW candidates (redundant) ----
        float4 cb[NW];
        float  ca[NW];
#pragma unroll
        for (int w = 0; w < NW; ++w) {
            cb[w] = s_allbox[jw[w]];
            ca[w] = (cb[w].z - cb[w].x) * (cb[w].w - cb[w].y);
        }
        bool acc[NW];
#pragma unroll
        for (int w = 0; w < NW; ++w) {
            bool a = (kw[w] != 0u);
#pragma unroll
            for (int v = 0; v < NW; ++v) {
                if (v >= w) break;
                // winner = cb[v] (accepted earlier), other = cb[w]
                float tlx = fmaxf(cb[w].x, cb[v].x);
                float tly = fmaxf(cb[w].y, cb[v].y);
                float brx = fminf(cb[w].z, cb[v].z);
                float bry = fminf(cb[w].w, cb[v].w);
                float iw = fmaxf(brx - tlx, 0.f);
                float ih = fmaxf(bry - tly, 0.f);
                float inter = iw * ih;
                float rhs = ca[v] + 1e-9f;
                bool ov = (3.f * inter > rhs + ca[w]);
                if (acc[v] && ov) a = false;
            }
            acc[w] = a;
        }

        // ---- emit accepted winners in order ----
#pragma unroll
        for (int w = 0; w < NW; ++w) {
            if (kw[w] == 0u) { exhausted = true; break; }
            if (acc[w] && emitted < MAXOUT) {
                if (t == 0) { s_selj[emitted] = jw[w]; s_selk[emitted] = kw[w]; }
                ++emitted;
            }
        }
        if (emitted >= MAXOUT) break;

        // ---- sentinel-ize non-accepted candidates ----
        float4 W[NW];
        float  rhsw[NW];
#pragma unroll
        for (int w = 0; w < NW; ++w) {
            if (acc[w]) {
                W[w] = cb[w];
                rhsw[w] = ca[w] + 1e-9f;
            } else {
                W[w] = make_float4(1e30f, 1e30f, 1e30f, 1e30f);
                rhsw[w] = 1e-9f;
            }
        }

        // ---- fused suppression vs up to NW winners + next local argmax ----
        lk = 0u; li = 0;
#pragma unroll
        for (int k = 0; k < KPT; ++k) {
            if (!((alive >> k) & 1u)) continue;      // warp-uniform skip
            float4 a = bx[k];
            unsigned kk = ky[k];
            float a2 = (a.z - a.x) * (a.w - a.y);
            bool sup = false;
#pragma unroll
            for (int w = 0; w < NW; ++w) {
                float tlx = fmaxf(a.x, W[w].x);
                float tly = fmaxf(a.y, W[w].y);
                float brx = fminf(a.z, W[w].z);
                float bry = fminf(a.w, W[w].w);
                float iw = fmaxf(brx - tlx, 0.f);
                float ih = fmaxf(bry - tly, 0.f);
                float inter = iw * ih;
                sup = sup || (3.f * inter > rhsw[w] + a2);
            }
            kk = sup ? 0u : kk;
            ky[k] = kk;
            if (kk > lk) { lk = kk; li = t + k * TPB; }
            if (!__any_sync(0xffffffffu, kk != 0u))
                alive &= ~(1u << k);
        }
    }

    __syncthreads();

    // ---- fused gather: boxes | labels | scores ----
    if (t < MAXOUT) {
        int j = s_selj[t];
        unsigned key = s_selk[t];
        bool valid = (key != 0u);

        float4 bv = s_allbox[j];
        float  sv = __uint_as_float(key - 0x80000000u);
        int    lb = valid ? g_labels[(size_t)b * NANCH + j] : -1;
        if (!valid) { bv = make_float4(0.f, 0.f, 0.f, 0.f); sv = 0.f; }

        reinterpret_cast<float4*>(out)[b * MAXOUT + t] = bv;
        out[BATCH * MAXOUT * 4 + b * MAXOUT + t] = valid ? (float)lb : -1.f;
        out[BATCH * MAXOUT * 5 + b * MAXOUT + t] = sv;
    }
}

// ---------------------------------------------------------------------------
extern "C" void kernel_launch(void* const* d_in, const int* in_sizes, int n_in,
                              void* d_out, int out_size)
{
    const float* preds   = (const float*)d_in[0];
    const float* anchors = (const float*)d_in[1];

    static int attr_done = 0;
    if (!attr_done) {
        cudaFuncSetAttribute(decode_kernel,
                             cudaFuncAttributeMaxDynamicSharedMemorySize, DAANCH * 37 * 16);
        cudaFuncSetAttribute(nms_kernel,
                             cudaFuncAttributeMaxDynamicSharedMemorySize, NANCH * 16);
        attr_done = 1;
    }

    decode_kernel<<<(BATCH * NANCH) / DAANCH, DT, DAANCH * 37 * 16>>>(preds, anchors);
    nms_kernel<<<BATCH, TPB, NANCH * 16>>>((float*)d_out);
}

// round 6
// speedup vs baseline: 1.6058x; 1.6058x over previous
#include <cuda_runtime.h>
#include <cuda_bf16.h>
#include <cstdint>

#define BATCH  64
#define NANCH  8400
#define MAXOUT 100
#define TPB    512
#define KPT    17            // 512*17 = 8704 >= 8400
#define DT     512           // decode threads per CTA
#define DAANCH 128           // anchors per decode CTA (4 threads/anchor)

#define NBUCK  4096
#define BBASE  0xBE80        // bucket = clamp((key>>16) - BBASE, 0, 4095)
#define CAP    1024          // max candidates per tier
#define TARGET 512           // tier size target
#define NWRD   32            // mask words per row (CAP/32)

typedef unsigned long long ull;

// ---------------------------------------------------------------------------
// Scratch
// ---------------------------------------------------------------------------
__device__ float4   g_boxes[BATCH * NANCH];
__device__ unsigned g_keys [BATCH * NANCH];   // monotonic score keys (0 = invalid)
__device__ int      g_labels[BATCH * NANCH];

// ---------------------------------------------------------------------------
// Kernel 1: decode (unchanged from passing R5 kernel).
// ---------------------------------------------------------------------------
__global__ void __launch_bounds__(DT) decode_kernel(const float* __restrict__ preds,
                                                    const float* __restrict__ anchors)
{
    extern __shared__ float4 sbuf[];          // 128 * 37 float4 = 75776 B
    const int t   = threadIdx.x;
    const int cta = blockIdx.x;

    const float4* __restrict__ base =
        reinterpret_cast<const float4*>(preds) + (size_t)cta * DAANCH * 36;

    {
        int a = t / 36;
        int j = t - a * 36;
#pragma unroll
        for (int u = 0; u < 9; ++u) {
            sbuf[a * 37 + j] = base[t + u * DT];
            a += 14; j += 8;                   // += 512 = 14*36 + 8
            if (j >= 36) { j -= 36; ++a; }
        }
    }
    __syncthreads();

    const int an = t >> 2;
    const int h  = t & 3;
    const float4* mine = sbuf + an * 37;

    float d;
    {
        float v[16];
#pragma unroll
        for (int q = 0; q < 4; ++q) {
            float4 f = mine[h * 4 + q];
            v[q * 4 + 0] = f.x; v[q * 4 + 1] = f.y;
            v[q * 4 + 2] = f.z; v[q * 4 + 3] = f.w;
        }
        float m = v[0];
#pragma unroll
        for (int i = 1; i < 16; ++i) m = fmaxf(m, v[i]);
        float se = 0.f, ws = 0.f;
#pragma unroll
        for (int i = 0; i < 16; ++i) {
            float e = __expf(v[i] - m);
            se += e;
            ws = fmaf(e, (float)i, ws);
        }
        d = ws / se;
    }
    float dpart = __shfl_xor_sync(0xffffffffu, d, 2);

    float best = -3.402823466e38f;
    int lab = 0;
#pragma unroll
    for (int i = 0; i < 5; ++i) {
        float4 f = mine[16 + h * 5 + i];
        int c = h * 20 + 4 * i;
        if (f.x > best) { best = f.x; lab = c + 0; }
        if (f.y > best) { best = f.y; lab = c + 1; }
        if (f.z > best) { best = f.z; lab = c + 2; }
        if (f.w > best) { best = f.w; lab = c + 3; }
    }

    const int gid = cta * DAANCH + an;
    const int nn  = gid % NANCH;
    float4 av = reinterpret_cast<const float4*>(anchors)[nn];
    float aa = (h & 1) ? av.y : av.x;
    float ab = (h & 1) ? av.w : av.z;
    float hw = ab - aa;
    float c0 = (aa + ab) * 0.5f;
    float bc = (dpart - d) * 0.5f * hw + c0;
    float bh = (dpart + d) * hw;
    float lo = bc - bh * 0.5f;
    float hi = bc + bh * 0.5f;

    float olo = __shfl_xor_sync(0xffffffffu, lo, 1);
    float ohi = __shfl_xor_sync(0xffffffffu, hi, 1);

    {
        float ob = __shfl_xor_sync(0xffffffffu, best, 1);
        int   ol = __shfl_xor_sync(0xffffffffu, lab, 1);
        if (ob > best || (ob == best && ol < lab)) { best = ob; lab = ol; }
        ob = __shfl_xor_sync(0xffffffffu, best, 2);
        ol = __shfl_xor_sync(0xffffffffu, lab, 2);
        if (ob > best || (ob == best && ol < lab)) { best = ob; lab = ol; }
    }

    if (h == 0) {
        float4 box; box.x = lo; box.y = olo; box.z = hi; box.w = ohi;
        g_boxes[gid] = box;
    } else if (h == 1) {
        g_keys[gid] = (best > 0.3f) ? (__float_as_uint(best) + 0x80000000u) : 0u;
    } else if (h == 2) {
        g_labels[gid] = lab;
    }
}

// ---------------------------------------------------------------------------
// Kernel 2: sort-then-mask greedy NMS (exact). One CTA per image.
// Tiered candidate selection by key histogram; bitonic sort per tier;
// triangular suppression bit-matrix; single-warp serial emit.
// ---------------------------------------------------------------------------
__global__ void __launch_bounds__(TPB, 1) nms_kernel(float* __restrict__ out)
{
    extern __shared__ unsigned char dyn[];
    ull*      skey  = (ull*)dyn;                          // CAP * 8      = 8192
    float4*   sbox  = (float4*)(dyn + 8192);              // CAP * 16     = 16384
    unsigned* smask = (unsigned*)(dyn + 8192 + 16384);    // CAP*NWRD*4   = 131072

    __shared__ int      hist[NBUCK];                      // 16 KB
    __shared__ int      blocksum[NBUCK / 32];
    __shared__ float4   s_wbox[MAXOUT];
    __shared__ float    s_warea[MAXOUT];
    __shared__ int      s_wjidx[MAXOUT];
    __shared__ unsigned s_wkey[MAXOUT];
    __shared__ unsigned psup[NWRD];
    __shared__ unsigned ssup[NWRD];
    __shared__ int      s_scount, s_L, s_cnt, s_W;

    const int b    = blockIdx.x;
    const int t    = threadIdx.x;
    const int warp = t >> 5;
    const int lane = t & 31;

    const float4*   __restrict__ gb = g_boxes + (size_t)b * NANCH;
    const unsigned* __restrict__ gk = g_keys  + (size_t)b * NANCH;

    // ---- histogram of keys ----
    for (int i = t; i < NBUCK; i += TPB) hist[i] = 0;
    __syncthreads();

    unsigned ky[KPT];
#pragma unroll
    for (int k = 0; k < KPT; ++k) {
        int idx = t + k * TPB;
        unsigned kk = (idx < NANCH) ? gk[idx] : 0u;
        ky[k] = kk;
        if (kk) {
            int bkt = (int)(kk >> 16) - BBASE;
            bkt = max(0, min(NBUCK - 1, bkt));
            atomicAdd(&hist[bkt], 1);
        }
    }
    __syncthreads();
    if (t < NBUCK / 32) {
        int s = 0;
#pragma unroll
        for (int q = 0; q < 32; ++q) s += hist[t * 32 + q];
        blocksum[t] = s;
    }
    if (t == 0) s_W = 0;
    __syncthreads();

    int U = NBUCK;                 // exclusive upper bucket of next tier
    int W = 0;

    for (int tier = 0; tier < 32 && W < MAXOUT; ++tier) {
        // ---- (a) tier threshold search (thread 0, block-skip) ----
        if (t == 0) {
            int bb = U, cum = 0;
            while (bb > 0) {
                if ((bb & 31) == 0) {
                    int blk = (bb >> 5) - 1;
                    int bs = blocksum[blk];
                    if (bs == 0) { bb -= 32; continue; }
                    if (cum + bs <= CAP && cum + bs < TARGET) { cum += bs; bb -= 32; continue; }
                }
                int h = hist[bb - 1];
                if (cum > 0 && cum + h > CAP) break;
                cum += h; --bb;
                if (cum >= TARGET) break;
            }
            s_L = bb; s_cnt = cum; s_scount = 0;
        }
        // zero candidate buffers
        for (int i = t; i < CAP; i += TPB) skey[i] = 0ull;
        if (t < NWRD) { psup[t] = 0u; ssup[t] = 0u; }
        __syncthreads();

        const int L = s_L;
        if (s_cnt == 0) break;     // no candidates left anywhere

        // ---- (b) compact tier candidates ----
#pragma unroll
        for (int k = 0; k < KPT; ++k) {
            unsigned kk = ky[k];
            if (!kk) continue;
            int bkt = (int)(kk >> 16) - BBASE;
            bkt = max(0, min(NBUCK - 1, bkt));
            if (bkt >= L && bkt < U) {
                int p = atomicAdd(&s_scount, 1);
                if (p < CAP)
                    skey[p] = ((ull)kk << 32) | (unsigned)(NANCH - (t + k * TPB));
            }
        }
        __syncthreads();
        const int scount = min(s_scount, CAP);
        const int nw = (scount + 31) >> 5;

        // ---- (c) bitonic sort descending, 1024 fixed ----
        for (unsigned kk = 2; kk <= CAP; kk <<= 1) {
            for (unsigned j = kk >> 1; j; j >>= 1) {
                unsigned p = (unsigned)t;
                unsigned i = ((p & ~(j - 1)) << 1) | (p & (j - 1));
                unsigned l = i | j;
                ull a = skey[i], bv = skey[l];
                bool desc = ((i & kk) == 0);
                if ((a < bv) == desc) { skey[i] = bv; skey[l] = a; }
                __syncthreads();
            }
        }

        // ---- (d) gather boxes ----
        for (int i = t; i < scount; i += TPB) {
            int gidx = NANCH - (int)(skey[i] & 0xffffffffu);
            sbox[i] = gb[gidx];
        }
        __syncthreads();

        // ---- (e) pre-suppression vs winners from earlier tiers ----
        if (W > 0) {
            for (int i = t; i < scount; i += TPB) {
                float4 a = sbox[i];
                float ai = (a.z - a.x) * (a.w - a.y);
                bool sup = false;
                for (int w = 0; w < W; ++w) {
                    float4 wbx = s_wbox[w];
                    float tlx = fmaxf(a.x, wbx.x);
                    float tly = fmaxf(a.y, wbx.y);
                    float brx = fminf(a.z, wbx.z);
                    float bry = fminf(a.w, wbx.w);
                    float iw = fmaxf(brx - tlx, 0.f);
                    float ih = fmaxf(bry - tly, 0.f);
                    float inter = iw * ih;
                    float rhs = s_warea[w] + 1e-9f;
                    sup = sup || (3.f * inter > rhs + ai);
                }
                if (sup) atomicOr(&psup[i >> 5], 1u << (i & 31));
            }
        }
        __syncthreads();

        // ---- (f) triangular mask: row i bit j (j>i) = "i suppresses j" ----
        for (int ii = 0; ii < CAP / TPB; ++ii) {
            int i = t + ii * TPB;
            if (i >= scount) continue;
            float4 bi = sbox[i];
            float ai = (bi.z - bi.x) * (bi.w - bi.y);
            float rhs = ai + 1e-9f;
            for (int wb = 0; wb < nw; ++wb) {
                int j0 = wb << 5;
                unsigned word = 0u;
                if (j0 + 31 > i) {
#pragma unroll 8
                    for (int l = 0; l < 32; ++l) {
                        int j = j0 + l;
                        float4 a = sbox[j & (CAP - 1)];
                        float tlx = fmaxf(a.x, bi.x);
                        float tly = fmaxf(a.y, bi.y);
                        float brx = fminf(a.z, bi.z);
                        float bry = fminf(a.w, bi.w);
                        float iw = fmaxf(brx - tlx, 0.f);
                        float ih = fmaxf(bry - tly, 0.f);
                        float inter = iw * ih;
                        float aj = (a.z - a.x) * (a.w - a.y);
                        bool sup = (3.f * inter > rhs + aj) && (j > i) && (j < scount);
                        word |= (sup ? 1u : 0u) << l;
                    }
                }
                smask[i * NWRD + wb] = word;
            }
        }
        __syncthreads();

        // ---- (g) serial greedy emit (warp 0) ----
        if (warp == 0) {
            if (lane < NWRD) ssup[lane] = psup[lane];
            __syncwarp();
            int Wl = W;
            for (int wi = 0; wi < nw && Wl < MAXOUT; ++wi) {
                int lim = scount - (wi << 5);
                unsigned validm = (lim >= 32) ? 0xffffffffu : ((1u << lim) - 1u);
                while (Wl < MAXOUT) {
                    unsigned live = (~ssup[wi]) & validm;
                    if (!live) break;
                    int bpos = __ffs(live) - 1;
                    int i = (wi << 5) + bpos;
                    unsigned v = (lane < nw) ? smask[i * NWRD + lane] : 0u;
                    if (lane == wi) v |= (1u << bpos);
                    if (lane < NWRD) ssup[lane] |= v;
                    if (lane == 0) {
                        ull e = skey[i];
                        s_wjidx[Wl] = NANCH - (int)(e & 0xffffffffu);
                        s_wkey[Wl]  = (unsigned)(e >> 32);
                        float4 bb = sbox[i];
                        s_wbox[Wl] = bb;
                        s_warea[Wl] = (bb.z - bb.x) * (bb.w - bb.y);
                    }
                    ++Wl;
                    __syncwarp();
                }
            }
            if (lane == 0) s_W = Wl;
        }
        __syncthreads();
        W = s_W;
        U = L;
    }

    // ---- output: boxes | labels | scores ----
    if (t < MAXOUT) {
        bool valid = (t < W);
        float4 bv = make_float4(0.f, 0.f, 0.f, 0.f);
        float  sv = 0.f;
        float  lb = -1.f;
        if (valid) {
            bv = s_wbox[t];
            sv = __uint_as_float(s_wkey[t] - 0x80000000u);
            lb = (float)g_labels[(size_t)b * NANCH + s_wjidx[t]];
        }
        reinterpret_cast<float4*>(out)[b * MAXOUT + t] = bv;
        out[BATCH * MAXOUT * 4 + b * MAXOUT + t] = lb;
        out[BATCH * MAXOUT * 5 + b * MAXOUT + t] = sv;
    }
}

// ---------------------------------------------------------------------------
extern "C" void kernel_launch(void* const* d_in, const int* in_sizes, int n_in,
                              void* d_out, int out_size)
{
    const float* preds   = (const float*)d_in[0];
    const float* anchors = (const float*)d_in[1];

    static int attr_done = 0;
    if (!attr_done) {
        cudaFuncSetAttribute(decode_kernel,
                             cudaFuncAttributeMaxDynamicSharedMemorySize, DAANCH * 37 * 16);
        cudaFuncSetAttribute(nms_kernel,
                             cudaFuncAttributeMaxDynamicSharedMemorySize,
                             8192 + 16384 + CAP * NWRD * 4);
        attr_done = 1;
    }

    decode_kernel<<<(BATCH * NANCH) / DAANCH, DT, DAANCH * 37 * 16>>>(preds, anchors);
    nms_kernel<<<BATCH, TPB, 8192 + 16384 + CAP * NWRD * 4>>>((float*)d_out);
}